// round 9
// baseline (speedup 1.0000x reference)
#include <cuda_runtime.h>
#include <cstdint>

// Problem constants (fixed by reference setup_inputs)
#define NB  8      // batch
#define CCH 512    // channels
#define NH  8      // heads
#define DD  64     // head dim
#define LL  64     // token length
#define CTK 256    // token channels
#define HW  16384  // 128*128 pixels

#define EPAD 132   // epilogue buffer row stride (floats)

// Scratch (device globals — no allocations allowed)
__device__ __align__(16) float g_k[NB * CCH * LL];  // [nh][l][d] tf32-rounded, pre-scaled 1/8
__device__ __align__(16) float g_v[NB * CCH * LL];  // [nh][d][l] tf32-rounded

__device__ __forceinline__ uint32_t f2tf32(float x) {
    uint32_t r;
    asm("cvt.rn.tf32.f32 %0, %1;" : "=r"(r) : "f"(x));
    return r;
}

// m16n8k8 tf32 HMMA (base-target instruction, works at compute_103)
__device__ __forceinline__ void mma_tf32(float* c,
                                         uint32_t a0, uint32_t a1, uint32_t a2, uint32_t a3,
                                         uint32_t b0, uint32_t b1) {
    asm volatile(
        "mma.sync.aligned.m16n8k8.row.col.f32.tf32.tf32.f32 "
        "{%0,%1,%2,%3}, {%4,%5,%6,%7}, {%8,%9}, {%0,%1,%2,%3};"
        : "+f"(c[0]), "+f"(c[1]), "+f"(c[2]), "+f"(c[3])
        : "r"(a0), "r"(a1), "r"(a2), "r"(a3), "r"(b0), "r"(b1));
}

// ============================================================================
// Kernel 1: fused V/K projections (1x1 conv, K=256).
// 256 blocks (8 n x 32 o-groups of 16), 256 threads (4 o x 64 l, 4 chunks).
// Weights for the 16 o's cached in smem; token slice stays L1-resident.
//   g_k[nh][l][d] = K/8 (tf32-rounded)  — GEMM1 B operand (k-dim = d)
//   g_v[nh][d][l] = V   (tf32-rounded)  — GEMM2 B operand (k-dim = l)
// ============================================================================
__global__ __launch_bounds__(256)
void vk_kernel(const float* __restrict__ token,
               const float* __restrict__ Wv, const float* __restrict__ bv,
               const float* __restrict__ Wk, const float* __restrict__ bk) {
    __shared__ float wv_s[16 * CTK];
    __shared__ float wk_s[16 * CTK];
    const int tid = threadIdx.x;
    const int n   = blockIdx.x >> 5;
    const int og  = blockIdx.x & 31;
    const int obase = og * 16;

#pragma unroll
    for (int i = 0; i < 16; i++) {
        wv_s[i * CTK + tid] = Wv[(obase + i) * CTK + tid];
        wk_s[i * CTK + tid] = Wk[(obase + i) * CTK + tid];
    }
    __syncthreads();

    const float* tok = token + n * (CTK * LL);
    const int l  = tid & 63;
    const int oc = tid >> 6;   // 0..3

#pragma unroll
    for (int c = 0; c < 4; c++) {
        const int ol = c * 4 + oc;
        const float* wv = wv_s + ol * CTK;
        const float* wk = wk_s + ol * CTK;
        float av0 = 0.f, av1 = 0.f, ak0 = 0.f, ak1 = 0.f;
#pragma unroll 8
        for (int ct = 0; ct < CTK; ct += 2) {
            float t0 = tok[ct * LL + l];
            float t1 = tok[(ct + 1) * LL + l];
            av0 = fmaf(wv[ct],     t0, av0);
            ak0 = fmaf(wk[ct],     t0, ak0);
            av1 = fmaf(wv[ct + 1], t1, av1);
            ak1 = fmaf(wk[ct + 1], t1, ak1);
        }
        const int o = obase + ol;
        float av = av0 + av1 + bv[o];
        float ak = (ak0 + ak1 + bk[o]) * 0.125f;  // 1/sqrt(C/h) = 1/8

        const int h = o >> 6, d = o & 63;
        const int slice = (n * NH + h) * (DD * LL);
        g_k[slice + l * DD + d] = __uint_as_float(f2tf32(ak));  // [l][d]
        g_v[slice + d * LL + l] = __uint_as_float(f2tf32(av));  // [d][l]
    }
}

// ============================================================================
// Kernel 2: mma.sync tf32 attention, M=32 per warp, one 128-px tile per CTA.
// CTA = 128 threads = 128 pixels of one (n,h); grid = 64 * 128 = 8192.
// Pixel permutation: MMA row r <-> local px 2*(r&7)+(r>>3), so Q fragments
// load as float2 (LDG.64) and GEMM2 outputs pair into float2 epilogue stores
// (conflict-free per 16-lane phase).
// Smem: ks/vs staging reused as epilogue transpose buffer after GEMM2.
// ============================================================================
__global__ __launch_bounds__(128, 3)
void attn_kernel(const float* __restrict__ feature, float* __restrict__ out) {
    __shared__ __align__(16) float sm[64 * EPAD];   // K/V staging, then epi buffer
    float* ks = sm;                                  // [64 l][64 d] packed-pair rotated
    float* vs = sm + 4096;                           // [64 d][64 l] packed-pair rotated

    const int tid  = threadIdx.x;
    const int lane = tid & 31;
    const int warp = tid >> 5;
    const int gid  = lane >> 2;   // fragment row group
    const int qid  = lane & 3;    // fragment col group
    const int nh   = blockIdx.x >> 7;
    const int tile = blockIdx.x & 127;

    // ---- stage K/V: (row, col) -> row*64 + 2*((4*(col/8)+(col&3)+4*row)&31) + ((col>>2)&1)
    {
        const float4* gk4 = reinterpret_cast<const float4*>(g_k) + nh * 1024;
        const float4* gv4 = reinterpret_cast<const float4*>(g_v) + nh * 1024;
#pragma unroll
        for (int i = 0; i < 8; i++) {
            int idx = tid + 128 * i;             // float4 index 0..1023
            int row = idx >> 4, c = idx & 15;
            int w = c & 1, ktb = 4 * (c >> 1) + 4 * row;
            float4 kv = gk4[idx];
            float4 vv = gv4[idx];
            float* kb = ks + row * 64 + w;
            float* vb = vs + row * 64 + w;
            kb[2 * ((ktb + 0) & 31)] = kv.x;  vb[2 * ((ktb + 0) & 31)] = vv.x;
            kb[2 * ((ktb + 1) & 31)] = kv.y;  vb[2 * ((ktb + 1) & 31)] = vv.y;
            kb[2 * ((ktb + 2) & 31)] = kv.z;  vb[2 * ((ktb + 2) & 31)] = vv.z;
            kb[2 * ((ktb + 3) & 31)] = kv.w;  vb[2 * ((ktb + 3) & 31)] = vv.w;
        }
    }

    const float* f = feature + nh * (DD * HW) + tile * 128 + warp * 32;
    const int rot = (qid + 4 * gid) & 31;

    __syncthreads();

    // ---- GEMM1: acc[2 m-tiles][8 n-tiles][4]; Q frags via LDG.64 (px perm) ----
    float acc[64];
#pragma unroll
    for (int i = 0; i < 64; i++) acc[i] = 0.f;
#pragma unroll
    for (int kt = 0; kt < 8; kt++) {
        uint32_t a[2][4];
#pragma unroll
        for (int T = 0; T < 2; T++) {
            // row gid <-> px 2gid, row gid+8 <-> px 2gid+1 (within 16-px tile T)
            float2 q0 = *reinterpret_cast<const float2*>(f + (8 * kt + qid) * HW + 16 * T + 2 * gid);
            float2 q1 = *reinterpret_cast<const float2*>(f + (8 * kt + qid + 4) * HW + 16 * T + 2 * gid);
            a[T][0] = f2tf32(q0.x);   // (row gid,   col qid)
            a[T][1] = f2tf32(q0.y);   // (row gid+8, col qid)
            a[T][2] = f2tf32(q1.x);   // (row gid,   col qid+4)
            a[T][3] = f2tf32(q1.y);   // (row gid+8, col qid+4)
        }
        const int c2 = (4 * kt + rot) & 31;
#pragma unroll
        for (int j = 0; j < 8; j++) {
            float2 b = *reinterpret_cast<const float2*>(&ks[(8 * j + gid) * 64 + 2 * c2]);
            uint32_t b0 = __float_as_uint(b.x), b1 = __float_as_uint(b.y);
            mma_tf32(&acc[4 * j],      a[0][0], a[0][1], a[0][2], a[0][3], b0, b1);
            mma_tf32(&acc[32 + 4 * j], a[1][0], a[1][1], a[1][2], a[1][3], b0, b1);
        }
    }

    // ---- softmax per m-tile (rows gid via c0/c1, gid+8 via c2/c3) ----
#pragma unroll
    for (int T = 0; T < 2; T++) {
        float* ac = acc + 32 * T;
        float m0 = -1e30f, m1 = -1e30f;
#pragma unroll
        for (int j = 0; j < 8; j++) {
            m0 = fmaxf(m0, fmaxf(ac[4 * j + 0], ac[4 * j + 1]));
            m1 = fmaxf(m1, fmaxf(ac[4 * j + 2], ac[4 * j + 3]));
        }
        m0 = fmaxf(m0, __shfl_xor_sync(0xffffffffu, m0, 1));
        m0 = fmaxf(m0, __shfl_xor_sync(0xffffffffu, m0, 2));
        m1 = fmaxf(m1, __shfl_xor_sync(0xffffffffu, m1, 1));
        m1 = fmaxf(m1, __shfl_xor_sync(0xffffffffu, m1, 2));
        float s0 = 0.f, s1 = 0.f;
#pragma unroll
        for (int j = 0; j < 8; j++) {
            ac[4 * j + 0] = __expf(ac[4 * j + 0] - m0); s0 += ac[4 * j + 0];
            ac[4 * j + 1] = __expf(ac[4 * j + 1] - m0); s0 += ac[4 * j + 1];
            ac[4 * j + 2] = __expf(ac[4 * j + 2] - m1); s1 += ac[4 * j + 2];
            ac[4 * j + 3] = __expf(ac[4 * j + 3] - m1); s1 += ac[4 * j + 3];
        }
        s0 += __shfl_xor_sync(0xffffffffu, s0, 1);
        s0 += __shfl_xor_sync(0xffffffffu, s0, 2);
        s1 += __shfl_xor_sync(0xffffffffu, s1, 1);
        s1 += __shfl_xor_sync(0xffffffffu, s1, 2);
        const float inv0 = __frcp_rn(s0);
        const float inv1 = __frcp_rn(s1);
#pragma unroll
        for (int j = 0; j < 8; j++) {
            ac[4 * j + 0] = __uint_as_float(f2tf32(ac[4 * j + 0] * inv0));
            ac[4 * j + 1] = __uint_as_float(f2tf32(ac[4 * j + 1] * inv0));
            ac[4 * j + 2] = __uint_as_float(f2tf32(ac[4 * j + 2] * inv1));
            ac[4 * j + 3] = __uint_as_float(f2tf32(ac[4 * j + 3] * inv1));
        }
    }

    // ---- remap coef D-frag -> A-frag in place (row-preserving; perm-safe) ----
    {
        const int s0 = 4 * gid + (qid >> 1);
        const int s1 = s0 + 2;
        const bool odd = qid & 1;
#pragma unroll
        for (int T = 0; T < 2; T++) {
            float* ac = acc + 32 * T;
#pragma unroll
            for (int t = 0; t < 8; t++) {
                float v0 = __shfl_sync(0xffffffffu, ac[4 * t + 0], s0);
                float v1 = __shfl_sync(0xffffffffu, ac[4 * t + 1], s0);
                float v2 = __shfl_sync(0xffffffffu, ac[4 * t + 2], s0);
                float v3 = __shfl_sync(0xffffffffu, ac[4 * t + 3], s0);
                float w0 = __shfl_sync(0xffffffffu, ac[4 * t + 0], s1);
                float w1 = __shfl_sync(0xffffffffu, ac[4 * t + 1], s1);
                float w2 = __shfl_sync(0xffffffffu, ac[4 * t + 2], s1);
                float w3 = __shfl_sync(0xffffffffu, ac[4 * t + 3], s1);
                ac[4 * t + 0] = odd ? v1 : v0;
                ac[4 * t + 1] = odd ? v3 : v2;
                ac[4 * t + 2] = odd ? w1 : w0;
                ac[4 * t + 3] = odd ? w3 : w2;
            }
        }
    }

    // ---- GEMM2: pr[2][8 d-tiles][4] = coef * V^T ----
    float pr[64];
#pragma unroll
    for (int i = 0; i < 64; i++) pr[i] = 0.f;
#pragma unroll
    for (int t = 0; t < 8; t++) {
        const int c2 = (4 * t + rot) & 31;
#pragma unroll
        for (int j = 0; j < 8; j++) {
            float2 b = *reinterpret_cast<const float2*>(&vs[(8 * j + gid) * 64 + 2 * c2]);
            uint32_t b0 = __float_as_uint(b.x), b1 = __float_as_uint(b.y);
            mma_tf32(&pr[4 * j],
                     __float_as_uint(acc[4 * t + 0]), __float_as_uint(acc[4 * t + 1]),
                     __float_as_uint(acc[4 * t + 2]), __float_as_uint(acc[4 * t + 3]), b0, b1);
            mma_tf32(&pr[32 + 4 * j],
                     __float_as_uint(acc[32 + 4 * t + 0]), __float_as_uint(acc[32 + 4 * t + 1]),
                     __float_as_uint(acc[32 + 4 * t + 2]), __float_as_uint(acc[32 + 4 * t + 3]), b0, b1);
        }
    }

    // ---- epilogue: D-frags -> sm via STS.64 pairs, then coalesced pass ----
    __syncthreads();   // K/V tiles dead for all warps
#pragma unroll
    for (int T = 0; T < 2; T++) {
#pragma unroll
        for (int j = 0; j < 8; j++) {
            int px = warp * 32 + 16 * T + 2 * gid;   // (c0,c2) = px, px+1 at same d
            int d  = 8 * j + 2 * qid;
            *reinterpret_cast<float2*>(&sm[d * EPAD + px]) =
                make_float2(pr[32 * T + 4 * j + 0], pr[32 * T + 4 * j + 2]);
            *reinterpret_cast<float2*>(&sm[(d + 1) * EPAD + px]) =
                make_float2(pr[32 * T + 4 * j + 1], pr[32 * T + 4 * j + 3]);
        }
    }
    __syncthreads();

    {
        const float* fb = feature + nh * (DD * HW) + tile * 128;
        float*       ob = out     + nh * (DD * HW) + tile * 128;
        const int px4 = lane * 4;
#pragma unroll
        for (int i = 0; i < 16; i++) {
            int d = warp * 16 + i;
            float4 p  = *reinterpret_cast<const float4*>(&sm[d * EPAD + px4]);
            float4 fv = *reinterpret_cast<const float4*>(&fb[d * HW + px4]);
            float4 ov;
            ov.x = fv.x + p.x; ov.y = fv.y + p.y;
            ov.z = fv.z + p.z; ov.w = fv.w + p.w;
            *reinterpret_cast<float4*>(&ob[d * HW + px4]) = ov;
        }
    }
}

// ============================================================================
extern "C" void kernel_launch(void* const* d_in, const int* in_sizes, int n_in,
                              void* d_out, int out_size) {
    const float* feature = (const float*)d_in[0];
    const float* token   = (const float*)d_in[1];
    const float* Wv      = (const float*)d_in[2];
    const float* bv      = (const float*)d_in[3];
    const float* Wk      = (const float*)d_in[4];
    const float* bk      = (const float*)d_in[5];
    float* out = (float*)d_out;

    vk_kernel<<<256, 256>>>(token, Wv, bv, Wk, bk);
    attn_kernel<<<NB * NH * 128, 128>>>(feature, out);
}

// round 10
// speedup vs baseline: 1.0192x; 1.0192x over previous
#include <cuda_runtime.h>
#include <cstdint>

// Problem constants (fixed by reference setup_inputs)
#define NB  8      // batch
#define CCH 512    // channels
#define NH  8      // heads
#define DD  64     // head dim
#define LL  64     // token length
#define CTK 256    // token channels
#define HW  16384  // 128*128 pixels

#define EPAD 132   // epilogue buffer row stride (floats)

// Scratch (device globals — no allocations allowed)
__device__ __align__(16) float g_k[NB * CCH * LL];  // [nh][l][d] tf32-rounded, pre-scaled 1/8
__device__ __align__(16) float g_v[NB * CCH * LL];  // [nh][d][l] tf32-rounded

__device__ __forceinline__ uint32_t f2tf32(float x) {
    uint32_t r;
    asm("cvt.rn.tf32.f32 %0, %1;" : "=r"(r) : "f"(x));
    return r;
}

// m16n8k8 tf32 HMMA (base-target instruction, works at compute_103)
__device__ __forceinline__ void mma_tf32(float* c,
                                         uint32_t a0, uint32_t a1, uint32_t a2, uint32_t a3,
                                         uint32_t b0, uint32_t b1) {
    asm volatile(
        "mma.sync.aligned.m16n8k8.row.col.f32.tf32.tf32.f32 "
        "{%0,%1,%2,%3}, {%4,%5,%6,%7}, {%8,%9}, {%0,%1,%2,%3};"
        : "+f"(c[0]), "+f"(c[1]), "+f"(c[2]), "+f"(c[3])
        : "r"(a0), "r"(a1), "r"(a2), "r"(a3), "r"(b0), "r"(b1));
}

// ============================================================================
// Kernel 1: fused V/K projections (1x1 conv, K=256).
// Grid 512 = 8n x 64 o-groups (8 o each); block 256 = 4 oc x 64 l.
// Each thread computes 2 outputs (o = obase+oc, obase+oc+4) as independent
// FMA chains; weights in smem (warp-broadcast reads); token loads coalesced,
// 32MB total L2 traffic.
//   g_k[nh][l][d] = K/8 (tf32-rounded)  — GEMM1 B operand (k-dim = d)
//   g_v[nh][d][l] = V   (tf32-rounded)  — GEMM2 B operand (k-dim = l)
// ============================================================================
__global__ __launch_bounds__(256)
void vk_kernel(const float* __restrict__ token,
               const float* __restrict__ Wv, const float* __restrict__ bv,
               const float* __restrict__ Wk, const float* __restrict__ bk) {
    __shared__ float wv_s[8 * CTK];
    __shared__ float wk_s[8 * CTK];
    const int tid = threadIdx.x;
    const int n     = blockIdx.x >> 6;
    const int obase = (blockIdx.x & 63) * 8;

#pragma unroll
    for (int i = 0; i < 8; i++) {
        wv_s[i * CTK + tid] = Wv[(obase + i) * CTK + tid];
        wk_s[i * CTK + tid] = Wk[(obase + i) * CTK + tid];
    }
    __syncthreads();

    const float* tok = token + n * (CTK * LL);
    const int l  = tid & 63;
    const int oc = tid >> 6;   // 0..3; whole warp shares one oc

    const float* wv0 = wv_s + oc * CTK;
    const float* wk0 = wk_s + oc * CTK;
    const float* wv1 = wv_s + (oc + 4) * CTK;
    const float* wk1 = wk_s + (oc + 4) * CTK;

    float av0 = 0.f, ak0 = 0.f, av1 = 0.f, ak1 = 0.f;
#pragma unroll 8
    for (int ct = 0; ct < CTK; ct++) {
        float t = tok[ct * LL + l];
        av0 = fmaf(wv0[ct], t, av0);
        ak0 = fmaf(wk0[ct], t, ak0);
        av1 = fmaf(wv1[ct], t, av1);
        ak1 = fmaf(wk1[ct], t, ak1);
    }

#pragma unroll
    for (int c = 0; c < 2; c++) {
        const int o = obase + oc + 4 * c;
        float av = (c ? av1 : av0) + bv[o];
        float ak = ((c ? ak1 : ak0) + bk[o]) * 0.125f;  // 1/sqrt(C/h) = 1/8
        const int h = o >> 6, d = o & 63;
        const int slice = (n * NH + h) * (DD * LL);
        g_k[slice + l * DD + d] = __uint_as_float(f2tf32(ak));  // [l][d]
        g_v[slice + d * LL + l] = __uint_as_float(f2tf32(av));  // [d][l]
    }
}

// ============================================================================
// Kernel 2: mma.sync tf32 attention, M=32 per warp, one 128-px tile per CTA.
// (unchanged from R9 measurement: 167.7us, best attn so far)
// CTA = 128 threads = 128 pixels of one (n,h); grid = 64 * 128 = 8192.
// Pixel permutation: MMA row r <-> local px 2*(r&7)+(r>>3), so Q fragments
// load as float2 (LDG.64) and GEMM2 outputs pair into float2 epilogue stores
// (conflict-free per 16-lane phase).
// ============================================================================
__global__ __launch_bounds__(128, 3)
void attn_kernel(const float* __restrict__ feature, float* __restrict__ out) {
    __shared__ __align__(16) float sm[64 * EPAD];   // K/V staging, then epi buffer
    float* ks = sm;                                  // [64 l][64 d] packed-pair rotated
    float* vs = sm + 4096;                           // [64 d][64 l] packed-pair rotated

    const int tid  = threadIdx.x;
    const int lane = tid & 31;
    const int warp = tid >> 5;
    const int gid  = lane >> 2;   // fragment row group
    const int qid  = lane & 3;    // fragment col group
    const int nh   = blockIdx.x >> 7;
    const int tile = blockIdx.x & 127;

    // ---- stage K/V: (row, col) -> row*64 + 2*((4*(col/8)+(col&3)+4*row)&31) + ((col>>2)&1)
    {
        const float4* gk4 = reinterpret_cast<const float4*>(g_k) + nh * 1024;
        const float4* gv4 = reinterpret_cast<const float4*>(g_v) + nh * 1024;
#pragma unroll
        for (int i = 0; i < 8; i++) {
            int idx = tid + 128 * i;             // float4 index 0..1023
            int row = idx >> 4, c = idx & 15;
            int w = c & 1, ktb = 4 * (c >> 1) + 4 * row;
            float4 kv = gk4[idx];
            float4 vv = gv4[idx];
            float* kb = ks + row * 64 + w;
            float* vb = vs + row * 64 + w;
            kb[2 * ((ktb + 0) & 31)] = kv.x;  vb[2 * ((ktb + 0) & 31)] = vv.x;
            kb[2 * ((ktb + 1) & 31)] = kv.y;  vb[2 * ((ktb + 1) & 31)] = vv.y;
            kb[2 * ((ktb + 2) & 31)] = kv.z;  vb[2 * ((ktb + 2) & 31)] = vv.z;
            kb[2 * ((ktb + 3) & 31)] = kv.w;  vb[2 * ((ktb + 3) & 31)] = vv.w;
        }
    }

    const float* f = feature + nh * (DD * HW) + tile * 128 + warp * 32;
    const int rot = (qid + 4 * gid) & 31;

    __syncthreads();

    // ---- GEMM1: acc[2 m-tiles][8 n-tiles][4]; Q frags via LDG.64 (px perm) ----
    float acc[64];
#pragma unroll
    for (int i = 0; i < 64; i++) acc[i] = 0.f;
#pragma unroll
    for (int kt = 0; kt < 8; kt++) {
        uint32_t a[2][4];
#pragma unroll
        for (int T = 0; T < 2; T++) {
            // row gid <-> px 2gid, row gid+8 <-> px 2gid+1 (within 16-px tile T)
            float2 q0 = *reinterpret_cast<const float2*>(f + (8 * kt + qid) * HW + 16 * T + 2 * gid);
            float2 q1 = *reinterpret_cast<const float2*>(f + (8 * kt + qid + 4) * HW + 16 * T + 2 * gid);
            a[T][0] = f2tf32(q0.x);   // (row gid,   col qid)
            a[T][1] = f2tf32(q0.y);   // (row gid+8, col qid)
            a[T][2] = f2tf32(q1.x);   // (row gid,   col qid+4)
            a[T][3] = f2tf32(q1.y);   // (row gid+8, col qid+4)
        }
        const int c2 = (4 * kt + rot) & 31;
#pragma unroll
        for (int j = 0; j < 8; j++) {
            float2 b = *reinterpret_cast<const float2*>(&ks[(8 * j + gid) * 64 + 2 * c2]);
            uint32_t b0 = __float_as_uint(b.x), b1 = __float_as_uint(b.y);
            mma_tf32(&acc[4 * j],      a[0][0], a[0][1], a[0][2], a[0][3], b0, b1);
            mma_tf32(&acc[32 + 4 * j], a[1][0], a[1][1], a[1][2], a[1][3], b0, b1);
        }
    }

    // ---- softmax per m-tile (rows gid via c0/c1, gid+8 via c2/c3) ----
#pragma unroll
    for (int T = 0; T < 2; T++) {
        float* ac = acc + 32 * T;
        float m0 = -1e30f, m1 = -1e30f;
#pragma unroll
        for (int j = 0; j < 8; j++) {
            m0 = fmaxf(m0, fmaxf(ac[4 * j + 0], ac[4 * j + 1]));
            m1 = fmaxf(m1, fmaxf(ac[4 * j + 2], ac[4 * j + 3]));
        }
        m0 = fmaxf(m0, __shfl_xor_sync(0xffffffffu, m0, 1));
        m0 = fmaxf(m0, __shfl_xor_sync(0xffffffffu, m0, 2));
        m1 = fmaxf(m1, __shfl_xor_sync(0xffffffffu, m1, 1));
        m1 = fmaxf(m1, __shfl_xor_sync(0xffffffffu, m1, 2));
        float s0 = 0.f, s1 = 0.f;
#pragma unroll
        for (int j = 0; j < 8; j++) {
            ac[4 * j + 0] = __expf(ac[4 * j + 0] - m0); s0 += ac[4 * j + 0];
            ac[4 * j + 1] = __expf(ac[4 * j + 1] - m0); s0 += ac[4 * j + 1];
            ac[4 * j + 2] = __expf(ac[4 * j + 2] - m1); s1 += ac[4 * j + 2];
            ac[4 * j + 3] = __expf(ac[4 * j + 3] - m1); s1 += ac[4 * j + 3];
        }
        s0 += __shfl_xor_sync(0xffffffffu, s0, 1);
        s0 += __shfl_xor_sync(0xffffffffu, s0, 2);
        s1 += __shfl_xor_sync(0xffffffffu, s1, 1);
        s1 += __shfl_xor_sync(0xffffffffu, s1, 2);
        const float inv0 = __frcp_rn(s0);
        const float inv1 = __frcp_rn(s1);
#pragma unroll
        for (int j = 0; j < 8; j++) {
            ac[4 * j + 0] = __uint_as_float(f2tf32(ac[4 * j + 0] * inv0));
            ac[4 * j + 1] = __uint_as_float(f2tf32(ac[4 * j + 1] * inv0));
            ac[4 * j + 2] = __uint_as_float(f2tf32(ac[4 * j + 2] * inv1));
            ac[4 * j + 3] = __uint_as_float(f2tf32(ac[4 * j + 3] * inv1));
        }
    }

    // ---- remap coef D-frag -> A-frag in place (row-preserving; perm-safe) ----
    {
        const int s0 = 4 * gid + (qid >> 1);
        const int s1 = s0 + 2;
        const bool odd = qid & 1;
#pragma unroll
        for (int T = 0; T < 2; T++) {
            float* ac = acc + 32 * T;
#pragma unroll
            for (int t = 0; t < 8; t++) {
                float v0 = __shfl_sync(0xffffffffu, ac[4 * t + 0], s0);
                float v1 = __shfl_sync(0xffffffffu, ac[4 * t + 1], s0);
                float v2 = __shfl_sync(0xffffffffu, ac[4 * t + 2], s0);
                float v3 = __shfl_sync(0xffffffffu, ac[4 * t + 3], s0);
                float w0 = __shfl_sync(0xffffffffu, ac[4 * t + 0], s1);
                float w1 = __shfl_sync(0xffffffffu, ac[4 * t + 1], s1);
                float w2 = __shfl_sync(0xffffffffu, ac[4 * t + 2], s1);
                float w3 = __shfl_sync(0xffffffffu, ac[4 * t + 3], s1);
                ac[4 * t + 0] = odd ? v1 : v0;
                ac[4 * t + 1] = odd ? v3 : v2;
                ac[4 * t + 2] = odd ? w1 : w0;
                ac[4 * t + 3] = odd ? w3 : w2;
            }
        }
    }

    // ---- GEMM2: pr[2][8 d-tiles][4] = coef * V^T ----
    float pr[64];
#pragma unroll
    for (int i = 0; i < 64; i++) pr[i] = 0.f;
#pragma unroll
    for (int t = 0; t < 8; t++) {
        const int c2 = (4 * t + rot) & 31;
#pragma unroll
        for (int j = 0; j < 8; j++) {
            float2 b = *reinterpret_cast<const float2*>(&vs[(8 * j + gid) * 64 + 2 * c2]);
            uint32_t b0 = __float_as_uint(b.x), b1 = __float_as_uint(b.y);
            mma_tf32(&pr[4 * j],
                     __float_as_uint(acc[4 * t + 0]), __float_as_uint(acc[4 * t + 1]),
                     __float_as_uint(acc[4 * t + 2]), __float_as_uint(acc[4 * t + 3]), b0, b1);
            mma_tf32(&pr[32 + 4 * j],
                     __float_as_uint(acc[32 + 4 * t + 0]), __float_as_uint(acc[32 + 4 * t + 1]),
                     __float_as_uint(acc[32 + 4 * t + 2]), __float_as_uint(acc[32 + 4 * t + 3]), b0, b1);
        }
    }

    // ---- epilogue: D-frags -> sm via STS.64 pairs, then coalesced pass ----
    __syncthreads();   // K/V tiles dead for all warps
#pragma unroll
    for (int T = 0; T < 2; T++) {
#pragma unroll
        for (int j = 0; j < 8; j++) {
            int px = warp * 32 + 16 * T + 2 * gid;   // (c0,c2) = px, px+1 at same d
            int d  = 8 * j + 2 * qid;
            *reinterpret_cast<float2*>(&sm[d * EPAD + px]) =
                make_float2(pr[32 * T + 4 * j + 0], pr[32 * T + 4 * j + 2]);
            *reinterpret_cast<float2*>(&sm[(d + 1) * EPAD + px]) =
                make_float2(pr[32 * T + 4 * j + 1], pr[32 * T + 4 * j + 3]);
        }
    }
    __syncthreads();

    {
        const float* fb = feature + nh * (DD * HW) + tile * 128;
        float*       ob = out     + nh * (DD * HW) + tile * 128;
        const int px4 = lane * 4;
#pragma unroll
        for (int i = 0; i < 16; i++) {
            int d = warp * 16 + i;
            float4 p  = *reinterpret_cast<const float4*>(&sm[d * EPAD + px4]);
            float4 fv = *reinterpret_cast<const float4*>(&fb[d * HW + px4]);
            float4 ov;
            ov.x = fv.x + p.x; ov.y = fv.y + p.y;
            ov.z = fv.z + p.z; ov.w = fv.w + p.w;
            *reinterpret_cast<float4*>(&ob[d * HW + px4]) = ov;
        }
    }
}

// ============================================================================
extern "C" void kernel_launch(void* const* d_in, const int* in_sizes, int n_in,
                              void* d_out, int out_size) {
    const float* feature = (const float*)d_in[0];
    const float* token   = (const float*)d_in[1];
    const float* Wv      = (const float*)d_in[2];
    const float* bv      = (const float*)d_in[3];
    const float* Wk      = (const float*)d_in[4];
    const float* bk      = (const float*)d_in[5];
    float* out = (float*)d_out;

    vk_kernel<<<512, 256>>>(token, Wv, bv, Wk, bk);
    attn_kernel<<<NB * NH * 128, 128>>>(feature, out);
}

// round 11
// speedup vs baseline: 1.1890x; 1.1665x over previous
#include <cuda_runtime.h>
#include <cstdint>

// Problem constants (fixed by reference setup_inputs)
#define NB  8      // batch
#define CCH 512    // channels
#define NH  8      // heads
#define DD  64     // head dim
#define LL  64     // token length
#define CTK 256    // token channels
#define HW  16384  // 128*128 pixels

#define EPAD 132   // epilogue buffer row stride (floats)

// Scratch (device globals — no allocations allowed).
// Stored PRE-SWIZZLED in the packed-pair rotated layout the attn kernel uses:
//   element (row, col) -> row*64 + 2*((4*(col>>3) + (col&3) + 4*row)&31) + ((col>>2)&1)
// g_k: row=l, col=d (K/8, tf32-rounded).  g_v: row=d, col=l (V, tf32-rounded).
__device__ __align__(16) float g_k[NB * CCH * LL];
__device__ __align__(16) float g_v[NB * CCH * LL];

__device__ __forceinline__ uint32_t f2tf32(float x) {
    uint32_t r;
    asm("cvt.rn.tf32.f32 %0, %1;" : "=r"(r) : "f"(x));
    return r;
}

// m16n8k8 tf32 HMMA (base-target instruction, works at compute_103)
__device__ __forceinline__ void mma_tf32(float* c,
                                         uint32_t a0, uint32_t a1, uint32_t a2, uint32_t a3,
                                         uint32_t b0, uint32_t b1) {
    asm volatile(
        "mma.sync.aligned.m16n8k8.row.col.f32.tf32.tf32.f32 "
        "{%0,%1,%2,%3}, {%4,%5,%6,%7}, {%8,%9}, {%0,%1,%2,%3};"
        : "+f"(c[0]), "+f"(c[1]), "+f"(c[2]), "+f"(c[3])
        : "r"(a0), "r"(a1), "r"(a2), "r"(a3), "r"(b0), "r"(b1));
}

// ============================================================================
// Kernel 1: fused V/K projections (1x1 conv, K=256). R1 structure (measured
// best); outputs written directly in the rotated packed-pair smem layout.
// Grid: 8*512 blocks, 64 threads (thread = l).
// ============================================================================
__global__ void vk_kernel(const float* __restrict__ token,
                          const float* __restrict__ Wv, const float* __restrict__ bv,
                          const float* __restrict__ Wk, const float* __restrict__ bk) {
    __shared__ float wv_s[CTK];
    __shared__ float wk_s[CTK];
    const int o = blockIdx.x & (CCH - 1);
    const int n = blockIdx.x >> 9;
    const int l = threadIdx.x;

#pragma unroll
    for (int i = 0; i < 4; i++) {
        wv_s[l + 64 * i] = Wv[o * CTK + l + 64 * i];
        wk_s[l + 64 * i] = Wk[o * CTK + l + 64 * i];
    }
    __syncthreads();

    const float* tok = token + n * (CTK * LL) + l;
    float av0 = 0.f, av1 = 0.f, ak0 = 0.f, ak1 = 0.f;
#pragma unroll 8
    for (int ct = 0; ct < CTK; ct += 2) {
        float t0 = tok[ct * LL];
        float t1 = tok[(ct + 1) * LL];
        av0 = fmaf(wv_s[ct],     t0, av0);
        ak0 = fmaf(wk_s[ct],     t0, ak0);
        av1 = fmaf(wv_s[ct + 1], t1, av1);
        ak1 = fmaf(wk_s[ct + 1], t1, ak1);
    }
    float av = av0 + av1 + bv[o];
    float ak = (ak0 + ak1 + bk[o]) * 0.125f;  // 1/sqrt(C/h) = 1/8

    const int h = o >> 6, d = o & 63;
    const int slice = (n * NH + h) * (DD * LL);
    // K: row=l, col=d — rotated packed-pair address
    const int ka = l * 64 + 2 * ((4 * (d >> 3) + (d & 3) + 4 * l) & 31) + ((d >> 2) & 1);
    // V: row=d, col=l
    const int va = d * 64 + 2 * ((4 * (l >> 3) + (l & 3) + 4 * d) & 31) + ((l >> 2) & 1);
    g_k[slice + ka] = __uint_as_float(f2tf32(ak));
    g_v[slice + va] = __uint_as_float(f2tf32(av));
}

// ============================================================================
// Kernel 2: mma.sync tf32 attention, M=32 per warp, one 128-px tile per CTA.
// (R9 attn, measured 167.7/167.8us; staging simplified to a straight float4
// copy since g_k/g_v are now pre-swizzled.)
// CTA = 128 threads = 128 pixels of one (n,h); grid = 64 * 128 = 8192.
// Pixel permutation: MMA row r <-> local px 2*(r&7)+(r>>3), so Q fragments
// load as float2 (LDG.64) and GEMM2 outputs pair into float2 epilogue stores.
// ============================================================================
__global__ __launch_bounds__(128, 3)
void attn_kernel(const float* __restrict__ feature, float* __restrict__ out) {
    __shared__ __align__(16) float sm[64 * EPAD];   // K/V staging, then epi buffer
    float* ks = sm;                                  // [64 l][64 d] packed-pair rotated
    float* vs = sm + 4096;                           // [64 d][64 l] packed-pair rotated

    const int tid  = threadIdx.x;
    const int lane = tid & 31;
    const int warp = tid >> 5;
    const int gid  = lane >> 2;   // fragment row group
    const int qid  = lane & 3;    // fragment col group
    const int nh   = blockIdx.x >> 7;
    const int tile = blockIdx.x & 127;

    // ---- stage K/V: plain float4 copy (layout already rotated in gmem) ----
    {
        const float4* gk4 = reinterpret_cast<const float4*>(g_k) + nh * 1024;
        const float4* gv4 = reinterpret_cast<const float4*>(g_v) + nh * 1024;
        float4* ks4 = reinterpret_cast<float4*>(ks);
        float4* vs4 = reinterpret_cast<float4*>(vs);
#pragma unroll
        for (int i = 0; i < 8; i++) {
            int idx = tid + 128 * i;
            ks4[idx] = gk4[idx];
            vs4[idx] = gv4[idx];
        }
    }

    const float* f = feature + nh * (DD * HW) + tile * 128 + warp * 32;
    const int rot = (qid + 4 * gid) & 31;

    __syncthreads();

    // ---- GEMM1: acc[2 m-tiles][8 n-tiles][4]; Q frags via LDG.64 (px perm) ----
    float acc[64];
#pragma unroll
    for (int i = 0; i < 64; i++) acc[i] = 0.f;
#pragma unroll
    for (int kt = 0; kt < 8; kt++) {
        uint32_t a[2][4];
#pragma unroll
        for (int T = 0; T < 2; T++) {
            // row gid <-> px 2gid, row gid+8 <-> px 2gid+1 (within 16-px tile T)
            float2 q0 = *reinterpret_cast<const float2*>(f + (8 * kt + qid) * HW + 16 * T + 2 * gid);
            float2 q1 = *reinterpret_cast<const float2*>(f + (8 * kt + qid + 4) * HW + 16 * T + 2 * gid);
            a[T][0] = f2tf32(q0.x);   // (row gid,   col qid)
            a[T][1] = f2tf32(q0.y);   // (row gid+8, col qid)
            a[T][2] = f2tf32(q1.x);   // (row gid,   col qid+4)
            a[T][3] = f2tf32(q1.y);   // (row gid+8, col qid+4)
        }
        const int c2 = (4 * kt + rot) & 31;
#pragma unroll
        for (int j = 0; j < 8; j++) {
            float2 b = *reinterpret_cast<const float2*>(&ks[(8 * j + gid) * 64 + 2 * c2]);
            uint32_t b0 = __float_as_uint(b.x), b1 = __float_as_uint(b.y);
            mma_tf32(&acc[4 * j],      a[0][0], a[0][1], a[0][2], a[0][3], b0, b1);
            mma_tf32(&acc[32 + 4 * j], a[1][0], a[1][1], a[1][2], a[1][3], b0, b1);
        }
    }

    // ---- softmax per m-tile (rows gid via c0/c1, gid+8 via c2/c3) ----
#pragma unroll
    for (int T = 0; T < 2; T++) {
        float* ac = acc + 32 * T;
        float m0 = -1e30f, m1 = -1e30f;
#pragma unroll
        for (int j = 0; j < 8; j++) {
            m0 = fmaxf(m0, fmaxf(ac[4 * j + 0], ac[4 * j + 1]));
            m1 = fmaxf(m1, fmaxf(ac[4 * j + 2], ac[4 * j + 3]));
        }
        m0 = fmaxf(m0, __shfl_xor_sync(0xffffffffu, m0, 1));
        m0 = fmaxf(m0, __shfl_xor_sync(0xffffffffu, m0, 2));
        m1 = fmaxf(m1, __shfl_xor_sync(0xffffffffu, m1, 1));
        m1 = fmaxf(m1, __shfl_xor_sync(0xffffffffu, m1, 2));
        float s0 = 0.f, s1 = 0.f;
#pragma unroll
        for (int j = 0; j < 8; j++) {
            ac[4 * j + 0] = __expf(ac[4 * j + 0] - m0); s0 += ac[4 * j + 0];
            ac[4 * j + 1] = __expf(ac[4 * j + 1] - m0); s0 += ac[4 * j + 1];
            ac[4 * j + 2] = __expf(ac[4 * j + 2] - m1); s1 += ac[4 * j + 2];
            ac[4 * j + 3] = __expf(ac[4 * j + 3] - m1); s1 += ac[4 * j + 3];
        }
        s0 += __shfl_xor_sync(0xffffffffu, s0, 1);
        s0 += __shfl_xor_sync(0xffffffffu, s0, 2);
        s1 += __shfl_xor_sync(0xffffffffu, s1, 1);
        s1 += __shfl_xor_sync(0xffffffffu, s1, 2);
        const float inv0 = __frcp_rn(s0);
        const float inv1 = __frcp_rn(s1);
#pragma unroll
        for (int j = 0; j < 8; j++) {
            ac[4 * j + 0] = __uint_as_float(f2tf32(ac[4 * j + 0] * inv0));
            ac[4 * j + 1] = __uint_as_float(f2tf32(ac[4 * j + 1] * inv0));
            ac[4 * j + 2] = __uint_as_float(f2tf32(ac[4 * j + 2] * inv1));
            ac[4 * j + 3] = __uint_as_float(f2tf32(ac[4 * j + 3] * inv1));
        }
    }

    // ---- remap coef D-frag -> A-frag in place (row-preserving; perm-safe) ----
    {
        const int s0 = 4 * gid + (qid >> 1);
        const int s1 = s0 + 2;
        const bool odd = qid & 1;
#pragma unroll
        for (int T = 0; T < 2; T++) {
            float* ac = acc + 32 * T;
#pragma unroll
            for (int t = 0; t < 8; t++) {
                float v0 = __shfl_sync(0xffffffffu, ac[4 * t + 0], s0);
                float v1 = __shfl_sync(0xffffffffu, ac[4 * t + 1], s0);
                float v2 = __shfl_sync(0xffffffffu, ac[4 * t + 2], s0);
                float v3 = __shfl_sync(0xffffffffu, ac[4 * t + 3], s0);
                float w0 = __shfl_sync(0xffffffffu, ac[4 * t + 0], s1);
                float w1 = __shfl_sync(0xffffffffu, ac[4 * t + 1], s1);
                float w2 = __shfl_sync(0xffffffffu, ac[4 * t + 2], s1);
                float w3 = __shfl_sync(0xffffffffu, ac[4 * t + 3], s1);
                ac[4 * t + 0] = odd ? v1 : v0;
                ac[4 * t + 1] = odd ? v3 : v2;
                ac[4 * t + 2] = odd ? w1 : w0;
                ac[4 * t + 3] = odd ? w3 : w2;
            }
        }
    }

    // ---- GEMM2: pr[2][8 d-tiles][4] = coef * V^T ----
    float pr[64];
#pragma unroll
    for (int i = 0; i < 64; i++) pr[i] = 0.f;
#pragma unroll
    for (int t = 0; t < 8; t++) {
        const int c2 = (4 * t + rot) & 31;
#pragma unroll
        for (int j = 0; j < 8; j++) {
            float2 b = *reinterpret_cast<const float2*>(&vs[(8 * j + gid) * 64 + 2 * c2]);
            uint32_t b0 = __float_as_uint(b.x), b1 = __float_as_uint(b.y);
            mma_tf32(&pr[4 * j],
                     __float_as_uint(acc[4 * t + 0]), __float_as_uint(acc[4 * t + 1]),
                     __float_as_uint(acc[4 * t + 2]), __float_as_uint(acc[4 * t + 3]), b0, b1);
            mma_tf32(&pr[32 + 4 * j],
                     __float_as_uint(acc[32 + 4 * t + 0]), __float_as_uint(acc[32 + 4 * t + 1]),
                     __float_as_uint(acc[32 + 4 * t + 2]), __float_as_uint(acc[32 + 4 * t + 3]), b0, b1);
        }
    }

    // ---- epilogue: D-frags -> sm via STS.64 pairs, then coalesced pass ----
    __syncthreads();   // K/V tiles dead for all warps
#pragma unroll
    for (int T = 0; T < 2; T++) {
#pragma unroll
        for (int j = 0; j < 8; j++) {
            int px = warp * 32 + 16 * T + 2 * gid;   // (c0,c2) = px, px+1 at same d
            int d  = 8 * j + 2 * qid;
            *reinterpret_cast<float2*>(&sm[d * EPAD + px]) =
                make_float2(pr[32 * T + 4 * j + 0], pr[32 * T + 4 * j + 2]);
            *reinterpret_cast<float2*>(&sm[(d + 1) * EPAD + px]) =
                make_float2(pr[32 * T + 4 * j + 1], pr[32 * T + 4 * j + 3]);
        }
    }
    __syncthreads();

    {
        const float* fb = feature + nh * (DD * HW) + tile * 128;
        float*       ob = out     + nh * (DD * HW) + tile * 128;
        const int px4 = lane * 4;
#pragma unroll
        for (int i = 0; i < 16; i++) {
            int d = warp * 16 + i;
            float4 p  = *reinterpret_cast<const float4*>(&sm[d * EPAD + px4]);
            float4 fv = *reinterpret_cast<const float4*>(&fb[d * HW + px4]);
            float4 ov;
            ov.x = fv.x + p.x; ov.y = fv.y + p.y;
            ov.z = fv.z + p.z; ov.w = fv.w + p.w;
            *reinterpret_cast<float4*>(&ob[d * HW + px4]) = ov;
        }
    }
}

// ============================================================================
extern "C" void kernel_launch(void* const* d_in, const int* in_sizes, int n_in,
                              void* d_out, int out_size) {
    const float* feature = (const float*)d_in[0];
    const float* token   = (const float*)d_in[1];
    const float* Wv      = (const float*)d_in[2];
    const float* bv      = (const float*)d_in[3];
    const float* Wk      = (const float*)d_in[4];
    const float* bk      = (const float*)d_in[5];
    float* out = (float*)d_out;

    vk_kernel<<<NB * CCH, 64>>>(token, Wv, bv, Wk, bk);
    attn_kernel<<<NB * NH * 128, 128>>>(feature, out);
}